// round 1
// baseline (speedup 1.0000x reference)
#include <cuda_runtime.h>
#include <math.h>

// Problem constants
#define LSEQ 2048
#define BATCH 64
#define EMB 256
#define HID 128
#define GATES 512          // 4*HID
#define NUTT 128           // LSEQ / 16
#define MROWS (NUTT*BATCH) // 8192

// Scratch (static device arrays; no allocation allowed)
__device__ float g_u[MROWS * EMB];          // pooled utterance embeddings [8192,256]  (8 MB)
__device__ float g_xp[MROWS * 1024];        // input-projected gates, both dirs [8192,1024] (32 MB)
__device__ float g_h[2 * MROWS * HID];      // hidden outputs per dir [2,8192,128] (8 MB)

__device__ __forceinline__ float sigf(float v) { return 1.0f / (1.0f + expf(-v)); }

// ---------------------------------------------------------------------------
// Kernel 1: mean-pool 16 token embeddings per utterance.
// grid (BATCH, NUTT), 256 threads (one per embedding dim).
// ---------------------------------------------------------------------------
__global__ void pool_kernel(const int* __restrict__ x, const float* __restrict__ emb)
{
    const int b = blockIdx.x;
    const int k = blockIdx.y;
    const int e = threadIdx.x;

    __shared__ int toks[16];
    if (e < 16) toks[e] = x[(k * 16 + e) * BATCH + b];
    __syncthreads();

    float acc = 0.0f;
#pragma unroll
    for (int i = 0; i < 16; i++) {
        acc += emb[(size_t)toks[i] * EMB + e];
    }
    g_u[(k * BATCH + b) * EMB + e] = acc * (1.0f / 16.0f);
}

// ---------------------------------------------------------------------------
// Kernel 2: xp[m, n] = sum_e u[m,e] * W[n,e] + bias[n], N = 1024 (both dirs).
// Classic fp32 tiled GEMM: 128x64 tile, BK=16, 256 threads, 8x4 micro-tile.
// Blocks never straddle the dir boundary (n0 multiple of 64, dirs at 512).
// ---------------------------------------------------------------------------
__global__ void __launch_bounds__(256) gemm_xp_kernel(
    const float* __restrict__ wf, const float* __restrict__ wb,
    const float* __restrict__ bif, const float* __restrict__ bhf,
    const float* __restrict__ bib, const float* __restrict__ bhb)
{
    __shared__ float As[16][132]; // k-major, padded
    __shared__ float Bs[16][68];

    const int n0 = blockIdx.x * 64;
    const int m0 = blockIdx.y * 128;

    const float* W;
    const float* bias1;
    const float* bias2;
    int nb;
    if (n0 < 512) { W = wf; bias1 = bif; bias2 = bhf; nb = n0; }
    else          { W = wb; bias1 = bib; bias2 = bhb; nb = n0 - 512; }

    const int tid = threadIdx.x;
    const int tx = tid & 15;   // 0..15 -> col group (4 cols)
    const int ty = tid >> 4;   // 0..15 -> row group (8 rows)

    const int aRow = tid >> 2;        // 0..63
    const int aC   = (tid & 3) * 4;   // 0,4,8,12

    float acc[8][4];
#pragma unroll
    for (int i = 0; i < 8; i++)
#pragma unroll
        for (int j = 0; j < 4; j++) acc[i][j] = 0.0f;

    for (int k0 = 0; k0 < EMB; k0 += 16) {
        const float4 a0 = *(const float4*)&g_u[(m0 + aRow) * EMB + k0 + aC];
        const float4 a1 = *(const float4*)&g_u[(m0 + aRow + 64) * EMB + k0 + aC];
        const float4 bv = *(const float4*)&W[(nb + aRow) * EMB + k0 + aC];
        __syncthreads();
        As[aC + 0][aRow] = a0.x; As[aC + 1][aRow] = a0.y;
        As[aC + 2][aRow] = a0.z; As[aC + 3][aRow] = a0.w;
        As[aC + 0][aRow + 64] = a1.x; As[aC + 1][aRow + 64] = a1.y;
        As[aC + 2][aRow + 64] = a1.z; As[aC + 3][aRow + 64] = a1.w;
        Bs[aC + 0][aRow] = bv.x; Bs[aC + 1][aRow] = bv.y;
        Bs[aC + 2][aRow] = bv.z; Bs[aC + 3][aRow] = bv.w;
        __syncthreads();

#pragma unroll
        for (int kk = 0; kk < 16; kk++) {
            const float4 ra0 = *(const float4*)&As[kk][ty * 8];
            const float4 ra1 = *(const float4*)&As[kk][ty * 8 + 4];
            const float4 rb  = *(const float4*)&Bs[kk][tx * 4];
            const float ra[8] = { ra0.x, ra0.y, ra0.z, ra0.w, ra1.x, ra1.y, ra1.z, ra1.w };
            const float rbv[4] = { rb.x, rb.y, rb.z, rb.w };
#pragma unroll
            for (int i = 0; i < 8; i++)
#pragma unroll
                for (int j = 0; j < 4; j++) acc[i][j] += ra[i] * rbv[j];
        }
    }

    // epilogue: add biases, store
    const int ncol = nb + tx * 4;
    const float4 b1 = *(const float4*)&bias1[ncol];
    const float4 b2 = *(const float4*)&bias2[ncol];
    const float badd[4] = { b1.x + b2.x, b1.y + b2.y, b1.z + b2.z, b1.w + b2.w };
#pragma unroll
    for (int i = 0; i < 8; i++) {
        const int m = m0 + ty * 8 + i;
        float4 v;
        v.x = acc[i][0] + badd[0];
        v.y = acc[i][1] + badd[1];
        v.z = acc[i][2] + badd[2];
        v.w = acc[i][3] + badd[3];
        *(float4*)&g_xp[(size_t)m * 1024 + n0 + tx * 4] = v;
    }
}

// ---------------------------------------------------------------------------
// Kernel 3: LSTM recurrence. One block per (dir, batch) = 128 blocks, 512 thr.
// w_hh cached fully on-SM: K columns 0..63 in registers (64/thread),
// K columns 64..127 in smem (k-major -> conflict-free lane access).
// ---------------------------------------------------------------------------
__global__ void __launch_bounds__(512) lstm_kernel(
    const float* __restrict__ whf, const float* __restrict__ whb)
{
    extern __shared__ float sm[];
    float* w2    = sm;                 // [64][512] = 128 KB
    float* h_sh  = sm + 64 * 512;      // [128]
    float* c_sh  = h_sh + 128;         // [128]
    float* gates = c_sh + 128;         // [512]

    const int bid = blockIdx.x;
    const int dir = bid >> 6;
    const int b   = bid & 63;
    const float* __restrict__ wh = dir ? whb : whf;
    const int j = threadIdx.x;

    float wreg[64];
#pragma unroll
    for (int k = 0; k < 64; k++) wreg[k] = wh[j * HID + k];
    for (int k = 0; k < 64; k++) w2[k * 512 + j] = wh[j * HID + 64 + k];

    if (j < HID) { h_sh[j] = 0.0f; c_sh[j] = 0.0f; }
    __syncthreads();

    for (int s = 0; s < NUTT; s++) {
        const int t = dir ? (NUTT - 1 - s) : s;
        float acc = g_xp[((size_t)t * BATCH + b) * 1024 + dir * 512 + j];

#pragma unroll
        for (int k4 = 0; k4 < 16; k4++) {
            const float4 hv = *(const float4*)&h_sh[k4 * 4];
            acc += wreg[k4 * 4 + 0] * hv.x;
            acc += wreg[k4 * 4 + 1] * hv.y;
            acc += wreg[k4 * 4 + 2] * hv.z;
            acc += wreg[k4 * 4 + 3] * hv.w;
        }
#pragma unroll
        for (int k4 = 0; k4 < 16; k4++) {
            const float4 hv = *(const float4*)&h_sh[64 + k4 * 4];
            acc += w2[(k4 * 4 + 0) * 512 + j] * hv.x;
            acc += w2[(k4 * 4 + 1) * 512 + j] * hv.y;
            acc += w2[(k4 * 4 + 2) * 512 + j] * hv.z;
            acc += w2[(k4 * 4 + 3) * 512 + j] * hv.w;
        }
        gates[j] = acc;
        __syncthreads();

        if (j < HID) {
            const float ig = sigf(gates[j]);
            const float fg = sigf(gates[128 + j]);
            const float gg = tanhf(gates[256 + j]);
            const float og = sigf(gates[384 + j]);
            const float c  = fg * c_sh[j] + ig * gg;
            c_sh[j] = c;
            const float h = og * tanhf(c);
            h_sh[j] = h;
            g_h[((size_t)dir * MROWS + (size_t)t * BATCH + b) * HID + j] = h;
        }
        __syncthreads();
    }
}

// ---------------------------------------------------------------------------
// Kernel 4a: output head. One warp per (t,b). Writes logits, policy,
// chosen_policy, u_mask into their sections of d_out (float32 layout).
// ---------------------------------------------------------------------------
__global__ void head_kernel(const float* __restrict__ wout,
                            const float* __restrict__ bout,
                            float* __restrict__ out)
{
    const int warp = threadIdx.x >> 5;
    const int lane = threadIdx.x & 31;
    const int m = blockIdx.x * 8 + warp;   // 0..8191
    if (m >= MROWS) return;

    const float* hf = g_h + (size_t)m * HID;
    const float* hb = g_h + ((size_t)MROWS + m) * HID;
    const int e = lane * 4;

    const float4 f4 = *(const float4*)&hf[e];
    const float4 b4 = *(const float4*)&hb[e];
    const float4 w0f = *(const float4*)&wout[0 * 256 + e];
    const float4 w0b = *(const float4*)&wout[0 * 256 + 128 + e];
    const float4 w1f = *(const float4*)&wout[1 * 256 + e];
    const float4 w1b = *(const float4*)&wout[1 * 256 + 128 + e];

    float l0 = f4.x * w0f.x + f4.y * w0f.y + f4.z * w0f.z + f4.w * w0f.w
             + b4.x * w0b.x + b4.y * w0b.y + b4.z * w0b.z + b4.w * w0b.w;
    float l1 = f4.x * w1f.x + f4.y * w1f.y + f4.z * w1f.z + f4.w * w1f.w
             + b4.x * w1b.x + b4.y * w1b.y + b4.z * w1b.z + b4.w * w1b.w;

#pragma unroll
    for (int off = 16; off > 0; off >>= 1) {
        l0 += __shfl_xor_sync(0xFFFFFFFFu, l0, off);
        l1 += __shfl_xor_sync(0xFFFFFFFFu, l1, off);
    }

    if (lane == 0) {
        l0 += bout[0];
        l1 += bout[1];
        const float mm = fmaxf(l0, l1);
        const float e0 = expf(l0 - mm);
        const float e1 = expf(l1 - mm);
        const float inv = 1.0f / (e0 + e1);
        const float p0 = e0 * inv;
        const float p1 = e1 * inv;
        const int idx = (l1 > l0) ? 1 : 0;   // argmax, first-index on tie

        out[m * 2 + 0] = l0;                 // logits
        out[m * 2 + 1] = l1;
        out[16384 + m * 2 + 0] = p0;         // policy
        out[16384 + m * 2 + 1] = p1;
        out[32768 + m] = idx ? p1 : p0;      // chosen_policy
        out[40960 + m] = (float)idx;         // u_mask (bool as 0/1)
    }
}

// ---------------------------------------------------------------------------
// Kernel 4b: expand utterance mask to tokens; masked_input section.
// ---------------------------------------------------------------------------
__global__ void mask_kernel(const int* __restrict__ x, float* __restrict__ out)
{
    const int i = blockIdx.x * 256 + threadIdx.x;  // i = t*64 + b, i < 131072
    if (i >= LSEQ * BATCH) return;
    const int b = i & 63;
    const int k = i >> 10;                         // (t/16)
    const float mv = out[40960 + k * 64 + b];      // u_mask written by head_kernel
    out[49152 + i] = (mv > 0.5f) ? (float)x[i] : 0.0f;
}

// ---------------------------------------------------------------------------
// Launch
// Inputs (metadata order): x, emb, w_ih_f, w_hh_f, b_ih_f, b_hh_f,
//                          w_ih_b, w_hh_b, b_ih_b, b_hh_b, w_out, b_out
// ---------------------------------------------------------------------------
extern "C" void kernel_launch(void* const* d_in, const int* in_sizes, int n_in,
                              void* d_out, int out_size)
{
    const int*   x     = (const int*)  d_in[0];
    const float* emb   = (const float*)d_in[1];
    const float* wih_f = (const float*)d_in[2];
    const float* whh_f = (const float*)d_in[3];
    const float* bih_f = (const float*)d_in[4];
    const float* bhh_f = (const float*)d_in[5];
    const float* wih_b = (const float*)d_in[6];
    const float* whh_b = (const float*)d_in[7];
    const float* bih_b = (const float*)d_in[8];
    const float* bhh_b = (const float*)d_in[9];
    const float* wout  = (const float*)d_in[10];
    const float* bout  = (const float*)d_in[11];
    float* out = (float*)d_out;

    // 1) pool
    pool_kernel<<<dim3(BATCH, NUTT), 256>>>(x, emb);

    // 2) input GEMM (both directions fused along N)
    gemm_xp_kernel<<<dim3(16, 64), 256>>>(wih_f, wih_b, bih_f, bhh_f, bih_b, bhh_b);

    // 3) recurrence (persistent per (dir,b) blocks, w_hh cached on-SM)
    const int lstm_smem = (64 * 512 + 128 + 128 + 512) * (int)sizeof(float); // 134144
    cudaFuncSetAttribute(lstm_kernel, cudaFuncAttributeMaxDynamicSharedMemorySize, lstm_smem);
    lstm_kernel<<<128, 512, lstm_smem>>>(whh_f, whh_b);

    // 4) head + mask expansion
    head_kernel<<<1024, 256>>>(wout, bout, out);
    mask_kernel<<<512, 256>>>(x, out);
}

// round 5
// speedup vs baseline: 1.0704x; 1.0704x over previous
#include <cuda_runtime.h>
#include <math.h>

// Problem constants
#define LSEQ 2048
#define BATCH 64
#define EMB 256
#define HID 128
#define NUTT 128           // LSEQ / 16
#define MROWS (NUTT*BATCH) // 8192

typedef unsigned long long ull;

// Scratch (static device arrays; no allocation allowed)
__device__ float g_u[MROWS * EMB];          // pooled utterance embeddings [8192,256]
__device__ float g_xp[MROWS * 1024];        // input-projected gates, both dirs [8192,1024]
__device__ float g_h[2 * MROWS * HID];      // hidden outputs per dir [2,8192,128]

__device__ __forceinline__ float sigf(float v) { return 1.0f / (1.0f + expf(-v)); }

// ---- packed f32x2 helpers (FFMA2: 2 exact fp32 FMAs per issue) ----
__device__ __forceinline__ ull pack2(float lo, float hi) {
    ull r; asm("mov.b64 %0, {%1,%2};" : "=l"(r) : "f"(lo), "f"(hi)); return r;
}
__device__ __forceinline__ void fma2(ull& d, ull a, ull b) {
    asm("fma.rn.f32x2 %0, %1, %2, %0;" : "+l"(d) : "l"(a), "l"(b));
}
__device__ __forceinline__ float2 unpack2(ull v) {
    float lo, hi; asm("mov.b64 {%0,%1}, %2;" : "=f"(lo), "=f"(hi) : "l"(v));
    return make_float2(lo, hi);
}

// ---------------------------------------------------------------------------
// Kernel 1: mean-pool 16 token embeddings per utterance.
// ---------------------------------------------------------------------------
__global__ void pool_kernel(const int* __restrict__ x, const float* __restrict__ emb)
{
    const int b = blockIdx.x;
    const int k = blockIdx.y;
    const int e = threadIdx.x;

    __shared__ int toks[16];
    if (e < 16) toks[e] = x[(k * 16 + e) * BATCH + b];
    __syncthreads();

    float acc = 0.0f;
#pragma unroll
    for (int i = 0; i < 16; i++) {
        acc += emb[(size_t)toks[i] * EMB + e];
    }
    g_u[(k * BATCH + b) * EMB + e] = acc * (1.0f / 16.0f);
}

// ---------------------------------------------------------------------------
// Kernel 2: xp[m,n] = sum_e u[m,e] * W[n,e] + bias[n], N=1024 (both dirs).
// 128x128 tile, BK=16, 256 threads, 8x8 micro-tile, packed f32x2 FMA.
// ---------------------------------------------------------------------------
__global__ void __launch_bounds__(256, 2) gemm_xp_kernel(
    const float* __restrict__ wf, const float* __restrict__ wb,
    const float* __restrict__ bif, const float* __restrict__ bhf,
    const float* __restrict__ bib, const float* __restrict__ bhb)
{
    __shared__ float As[16][132]; // k-major, padded
    __shared__ float Bs[16][132];

    const int n0 = blockIdx.x * 128;  // 8 blocks, never straddles dir boundary (512)
    const int m0 = blockIdx.y * 128;  // 64 blocks

    const float* W; const float* b1p; const float* b2p; int nb;
    if (n0 < 512) { W = wf; b1p = bif; b2p = bhf; nb = n0; }
    else          { W = wb; b1p = bib; b2p = bhb; nb = n0 - 512; }

    const int tid = threadIdx.x;
    const int tx = tid & 15;   // n-subtile: 8 cols (4 packed pairs)
    const int ty = tid >> 4;   // m-subtile: 8 rows

    const int ldRow = tid >> 1;        // 0..127
    const int ldC   = (tid & 1) * 8;   // 0 or 8

    ull acc[8][4];
#pragma unroll
    for (int i = 0; i < 8; i++)
#pragma unroll
        for (int j = 0; j < 4; j++) acc[i][j] = 0ull;

    for (int k0 = 0; k0 < EMB; k0 += 16) {
        const float4 a0 = *(const float4*)&g_u[(size_t)(m0 + ldRow) * EMB + k0 + ldC];
        const float4 a1 = *(const float4*)&g_u[(size_t)(m0 + ldRow) * EMB + k0 + ldC + 4];
        const float4 w0 = *(const float4*)&W[(size_t)(nb + ldRow) * EMB + k0 + ldC];
        const float4 w1 = *(const float4*)&W[(size_t)(nb + ldRow) * EMB + k0 + ldC + 4];
        __syncthreads();
        As[ldC + 0][ldRow] = a0.x; As[ldC + 1][ldRow] = a0.y;
        As[ldC + 2][ldRow] = a0.z; As[ldC + 3][ldRow] = a0.w;
        As[ldC + 4][ldRow] = a1.x; As[ldC + 5][ldRow] = a1.y;
        As[ldC + 6][ldRow] = a1.z; As[ldC + 7][ldRow] = a1.w;
        Bs[ldC + 0][ldRow] = w0.x; Bs[ldC + 1][ldRow] = w0.y;
        Bs[ldC + 2][ldRow] = w0.z; Bs[ldC + 3][ldRow] = w0.w;
        Bs[ldC + 4][ldRow] = w1.x; Bs[ldC + 5][ldRow] = w1.y;
        Bs[ldC + 6][ldRow] = w1.z; Bs[ldC + 7][ldRow] = w1.w;
        __syncthreads();

#pragma unroll
        for (int kk = 0; kk < 16; kk++) {
            const float4 ra0 = *(const float4*)&As[kk][ty * 8];
            const float4 ra1 = *(const float4*)&As[kk][ty * 8 + 4];
            const ull* bp = (const ull*)&Bs[kk][tx * 8];
            const ull b0 = bp[0], b1 = bp[1], b2 = bp[2], b3 = bp[3];
            const float a[8] = { ra0.x, ra0.y, ra0.z, ra0.w, ra1.x, ra1.y, ra1.z, ra1.w };
#pragma unroll
            for (int i = 0; i < 8; i++) {
                const ull ai = pack2(a[i], a[i]);
                fma2(acc[i][0], ai, b0);
                fma2(acc[i][1], ai, b1);
                fma2(acc[i][2], ai, b2);
                fma2(acc[i][3], ai, b3);
            }
        }
    }

    // epilogue: biases + store
    const int nc = nb + tx * 8;
    const float4 ba0 = *(const float4*)&b1p[nc];
    const float4 ba1 = *(const float4*)&b1p[nc + 4];
    const float4 bb0 = *(const float4*)&b2p[nc];
    const float4 bb1 = *(const float4*)&b2p[nc + 4];
    const float bias[8] = { ba0.x + bb0.x, ba0.y + bb0.y, ba0.z + bb0.z, ba0.w + bb0.w,
                            ba1.x + bb1.x, ba1.y + bb1.y, ba1.z + bb1.z, ba1.w + bb1.w };
#pragma unroll
    for (int i = 0; i < 8; i++) {
        const size_t m = m0 + ty * 8 + i;
        const float2 p0 = unpack2(acc[i][0]);
        const float2 p1 = unpack2(acc[i][1]);
        const float2 p2 = unpack2(acc[i][2]);
        const float2 p3 = unpack2(acc[i][3]);
        float4 v0, v1;
        v0.x = p0.x + bias[0]; v0.y = p0.y + bias[1];
        v0.z = p1.x + bias[2]; v0.w = p1.y + bias[3];
        v1.x = p2.x + bias[4]; v1.y = p2.y + bias[5];
        v1.z = p3.x + bias[6]; v1.w = p3.y + bias[7];
        *(float4*)&g_xp[m * 1024 + n0 + tx * 8]     = v0;
        *(float4*)&g_xp[m * 1024 + n0 + tx * 8 + 4] = v1;
    }
}

// ---------------------------------------------------------------------------
// Kernel 3: LSTM recurrence. One block per (dir,b) = 128 blocks, 512 threads.
// w_hh row j split: k[0..79] in registers (40 ull pairs), k[80..127] in smem
// (24 pairs, [k2][j] layout -> conflict-free). All matvec via FFMA2, no packs.
// ---------------------------------------------------------------------------
#define RP 40   // register k-pairs
#define SP 24   // smem k-pairs

__global__ void __launch_bounds__(512) lstm_kernel(
    const float* __restrict__ whf, const float* __restrict__ whb)
{
    extern __shared__ char smraw[];
    ull*   w2    = (ull*)smraw;                 // [SP][512]  = 96 KB
    float* h_sh  = (float*)(w2 + SP * 512);     // [128] (16B aligned)
    float* c_sh  = h_sh + 128;                  // [128]
    float* gates = c_sh + 128;                  // [512]

    const int bid = blockIdx.x;
    const int dir = bid >> 6;
    const int b   = bid & 63;
    const float* __restrict__ wh = dir ? whb : whf;
    const int j = threadIdx.x;

    ull wreg[RP];
    const ull* whu = (const ull*)(wh + (size_t)j * HID);  // row j as 64 k-pairs
#pragma unroll
    for (int k = 0; k < RP; k++) wreg[k] = whu[k];
    for (int k = 0; k < SP; k++) w2[k * 512 + j] = whu[RP + k];

    if (j < HID) { h_sh[j] = 0.0f; c_sh[j] = 0.0f; }
    __syncthreads();

    const int t0 = dir ? (NUTT - 1) : 0;
    float xpv = g_xp[((size_t)t0 * BATCH + b) * 1024 + dir * 512 + j];

    for (int s = 0; s < NUTT; s++) {
        const int t = dir ? (NUTT - 1 - s) : s;
        // prefetch next step's xp (off the critical path)
        float xp_next = 0.0f;
        if (s + 1 < NUTT) {
            const int tn = dir ? (NUTT - 2 - s) : (s + 1);
            xp_next = g_xp[((size_t)tn * BATCH + b) * 1024 + dir * 512 + j];
        }

        ull acc0 = pack2(xpv, 0.0f);
        ull acc1 = pack2(0.0f, 0.0f);
        const ulonglong2* hp = (const ulonglong2*)h_sh;  // 32 x (2 k-pairs)
#pragma unroll
        for (int q = 0; q < RP / 2; q++) {               // k pairs 0..39
            const ulonglong2 hv = hp[q];
            fma2(acc0, wreg[2 * q],     hv.x);
            fma2(acc1, wreg[2 * q + 1], hv.y);
        }
#pragma unroll
        for (int q = 0; q < SP / 2; q++) {               // k pairs 40..63
            const ulonglong2 hv = hp[RP / 2 + q];
            fma2(acc0, w2[(2 * q) * 512 + j],     hv.x);
            fma2(acc1, w2[(2 * q + 1) * 512 + j], hv.y);
        }
        const float2 s0 = unpack2(acc0);
        const float2 s1 = unpack2(acc1);
        gates[j] = (s0.x + s1.x) + (s0.y + s1.y);
        __syncthreads();

        if (j < HID) {
            const float ig = sigf(gates[j]);
            const float fg = sigf(gates[128 + j]);
            const float gg = tanhf(gates[256 + j]);
            const float og = sigf(gates[384 + j]);
            const float c  = fg * c_sh[j] + ig * gg;
            c_sh[j] = c;
            const float h = og * tanhf(c);
            h_sh[j] = h;
            g_h[((size_t)dir * MROWS + (size_t)t * BATCH + b) * HID + j] = h;
        }
        __syncthreads();
        xpv = xp_next;
    }
}

// ---------------------------------------------------------------------------
// Kernel 4a: output head. One warp per (t,b).
// ---------------------------------------------------------------------------
__global__ void head_kernel(const float* __restrict__ wout,
                            const float* __restrict__ bout,
                            float* __restrict__ out)
{
    const int warp = threadIdx.x >> 5;
    const int lane = threadIdx.x & 31;
    const int m = blockIdx.x * 8 + warp;
    if (m >= MROWS) return;

    const float* hf = g_h + (size_t)m * HID;
    const float* hb = g_h + ((size_t)MROWS + m) * HID;
    const int e = lane * 4;

    const float4 f4 = *(const float4*)&hf[e];
    const float4 b4 = *(const float4*)&hb[e];
    const float4 w0f = *(const float4*)&wout[e];
    const float4 w0b = *(const float4*)&wout[128 + e];
    const float4 w1f = *(const float4*)&wout[256 + e];
    const float4 w1b = *(const float4*)&wout[256 + 128 + e];

    float l0 = f4.x * w0f.x + f4.y * w0f.y + f4.z * w0f.z + f4.w * w0f.w
             + b4.x * w0b.x + b4.y * w0b.y + b4.z * w0b.z + b4.w * w0b.w;
    float l1 = f4.x * w1f.x + f4.y * w1f.y + f4.z * w1f.z + f4.w * w1f.w
             + b4.x * w1b.x + b4.y * w1b.y + b4.z * w1b.z + b4.w * w1b.w;

#pragma unroll
    for (int off = 16; off > 0; off >>= 1) {
        l0 += __shfl_xor_sync(0xFFFFFFFFu, l0, off);
        l1 += __shfl_xor_sync(0xFFFFFFFFu, l1, off);
    }

    if (lane == 0) {
        l0 += bout[0];
        l1 += bout[1];
        const float mm = fmaxf(l0, l1);
        const float e0 = expf(l0 - mm);
        const float e1 = expf(l1 - mm);
        const float inv = 1.0f / (e0 + e1);
        const float p0 = e0 * inv;
        const float p1 = e1 * inv;
        const int idx = (l1 > l0) ? 1 : 0;

        out[m * 2 + 0] = l0;
        out[m * 2 + 1] = l1;
        out[16384 + m * 2 + 0] = p0;
        out[16384 + m * 2 + 1] = p1;
        out[32768 + m] = idx ? p1 : p0;
        out[40960 + m] = (float)idx;
    }
}

// ---------------------------------------------------------------------------
// Kernel 4b: expand utterance mask to tokens.
// ---------------------------------------------------------------------------
__global__ void mask_kernel(const int* __restrict__ x, float* __restrict__ out)
{
    const int i = blockIdx.x * 256 + threadIdx.x;
    if (i >= LSEQ * BATCH) return;
    const int b = i & 63;
    const int k = i >> 10;
    const float mv = out[40960 + k * 64 + b];
    out[49152 + i] = (mv > 0.5f) ? (float)x[i] : 0.0f;
}

// ---------------------------------------------------------------------------
// Launch
// Inputs (metadata order): x, emb, w_ih_f, w_hh_f, b_ih_f, b_hh_f,
//                          w_ih_b, w_hh_b, b_ih_b, b_hh_b, w_out, b_out
// ---------------------------------------------------------------------------
extern "C" void kernel_launch(void* const* d_in, const int* in_sizes, int n_in,
                              void* d_out, int out_size)
{
    const int*   x     = (const int*)  d_in[0];
    const float* emb   = (const float*)d_in[1];
    const float* wih_f = (const float*)d_in[2];
    const float* whh_f = (const float*)d_in[3];
    const float* bih_f = (const float*)d_in[4];
    const float* bhh_f = (const float*)d_in[5];
    const float* wih_b = (const float*)d_in[6];
    const float* whh_b = (const float*)d_in[7];
    const float* bih_b = (const float*)d_in[8];
    const float* bhh_b = (const float*)d_in[9];
    const float* wout  = (const float*)d_in[10];
    const float* bout  = (const float*)d_in[11];
    float* out = (float*)d_out;

    pool_kernel<<<dim3(BATCH, NUTT), 256>>>(x, emb);

    gemm_xp_kernel<<<dim3(8, 64), 256>>>(wih_f, wih_b, bih_f, bhh_f, bih_b, bhh_b);

    const int lstm_smem = SP * 512 * (int)sizeof(ull) + (128 + 128 + 512) * (int)sizeof(float);
    cudaFuncSetAttribute(lstm_kernel, cudaFuncAttributeMaxDynamicSharedMemorySize, lstm_smem);
    lstm_kernel<<<128, 512, lstm_smem>>>(whh_f, whh_b);

    head_kernel<<<1024, 256>>>(wout, bout, out);
    mask_kernel<<<512, 256>>>(x, out);
}

// round 8
// speedup vs baseline: 1.0775x; 1.0066x over previous
#include <cuda_runtime.h>
#include <math.h>

// Problem constants
#define LSEQ 2048
#define BATCH 64
#define EMB 256
#define HID 128
#define NUTT 128           // LSEQ / 16
#define MROWS (NUTT*BATCH) // 8192

typedef unsigned long long ull;

// Scratch (static device arrays; no allocation allowed)
__device__ float g_u[MROWS * EMB];          // pooled utterance embeddings [8192,256]
__device__ float g_xp[MROWS * 1024];        // input-projected gates, both dirs [8192,1024]
__device__ float g_h[2 * MROWS * HID];      // hidden outputs per dir [2,8192,128]

__device__ __forceinline__ float sigf(float v) { return 1.0f / (1.0f + expf(-v)); }

// ---- packed f32x2 helpers (FFMA2: 2 exact fp32 FMAs per issue) ----
__device__ __forceinline__ ull pack2(float lo, float hi) {
    ull r; asm("mov.b64 %0, {%1,%2};" : "=l"(r) : "f"(lo), "f"(hi)); return r;
}
__device__ __forceinline__ void fma2(ull& d, ull a, ull b) {
    asm("fma.rn.f32x2 %0, %1, %2, %0;" : "+l"(d) : "l"(a), "l"(b));
}
__device__ __forceinline__ float2 unpack2(ull v) {
    float lo, hi; asm("mov.b64 {%0,%1}, %2;" : "=f"(lo), "=f"(hi) : "l"(v));
    return make_float2(lo, hi);
}

// ---------------------------------------------------------------------------
// Kernel 1: mean-pool 16 token embeddings per utterance.
// ---------------------------------------------------------------------------
__global__ void pool_kernel(const int* __restrict__ x, const float* __restrict__ emb)
{
    const int b = blockIdx.x;
    const int k = blockIdx.y;
    const int e = threadIdx.x;

    __shared__ int toks[16];
    if (e < 16) toks[e] = x[(k * 16 + e) * BATCH + b];
    __syncthreads();

    float acc = 0.0f;
#pragma unroll
    for (int i = 0; i < 16; i++) {
        acc += emb[(size_t)toks[i] * EMB + e];
    }
    g_u[(k * BATCH + b) * EMB + e] = acc * (1.0f / 16.0f);
}

// ---------------------------------------------------------------------------
// Dummy kernel: occupies launch slot 2 so the ncu capture slot (observed to be
// sequence position 3) lands on lstm_kernel instead of head_kernel.
// ---------------------------------------------------------------------------
__global__ void slot_kernel() {}

// ---------------------------------------------------------------------------
// Kernel 2: xp[m,n] = sum_e u[m,e] * W[n,e] + bias[n], N=1024 (both dirs).
// 128x128 tile, BK=16, 256 threads, 8x8 micro-tile, packed f32x2 FMA.
// Software-pipelined: double-buffered smem, LDG(k+1) overlaps compute(k),
// ONE __syncthreads per K-iteration.
// ---------------------------------------------------------------------------
__global__ void __launch_bounds__(256, 2) gemm_xp_kernel(
    const float* __restrict__ wf, const float* __restrict__ wb,
    const float* __restrict__ bif, const float* __restrict__ bhf,
    const float* __restrict__ bib, const float* __restrict__ bhb)
{
    __shared__ float As[2][16][132]; // k-major, padded
    __shared__ float Bs[2][16][132];

    const int n0 = blockIdx.x * 128;  // 8 blocks, never straddles dir boundary (512)
    const int m0 = blockIdx.y * 128;  // 64 blocks

    const float* W; const float* b1p; const float* b2p; int nb;
    if (n0 < 512) { W = wf; b1p = bif; b2p = bhf; nb = n0; }
    else          { W = wb; b1p = bib; b2p = bhb; nb = n0 - 512; }

    const int tid = threadIdx.x;
    const int tx = tid & 15;   // n-subtile: 8 cols (4 packed pairs)
    const int ty = tid >> 4;   // m-subtile: 8 rows

    const int ldRow = tid >> 1;        // 0..127
    const int ldC   = (tid & 1) * 8;   // 0 or 8

    const float* aBase = &g_u[(size_t)(m0 + ldRow) * EMB + ldC];
    const float* wBase = &W[(size_t)(nb + ldRow) * EMB + ldC];

    ull acc[8][4];
#pragma unroll
    for (int i = 0; i < 8; i++)
#pragma unroll
        for (int j = 0; j < 4; j++) acc[i][j] = 0ull;

    // prologue: load tile 0 into buffer 0
    {
        const float4 a0 = *(const float4*)(aBase + 0);
        const float4 a1 = *(const float4*)(aBase + 4);
        const float4 w0 = *(const float4*)(wBase + 0);
        const float4 w1 = *(const float4*)(wBase + 4);
        As[0][ldC + 0][ldRow] = a0.x; As[0][ldC + 1][ldRow] = a0.y;
        As[0][ldC + 2][ldRow] = a0.z; As[0][ldC + 3][ldRow] = a0.w;
        As[0][ldC + 4][ldRow] = a1.x; As[0][ldC + 5][ldRow] = a1.y;
        As[0][ldC + 6][ldRow] = a1.z; As[0][ldC + 7][ldRow] = a1.w;
        Bs[0][ldC + 0][ldRow] = w0.x; Bs[0][ldC + 1][ldRow] = w0.y;
        Bs[0][ldC + 2][ldRow] = w0.z; Bs[0][ldC + 3][ldRow] = w0.w;
        Bs[0][ldC + 4][ldRow] = w1.x; Bs[0][ldC + 5][ldRow] = w1.y;
        Bs[0][ldC + 6][ldRow] = w1.z; Bs[0][ldC + 7][ldRow] = w1.w;
    }
    __syncthreads();

#pragma unroll 1
    for (int k0i = 0; k0i < 16; k0i++) {
        const int cur = k0i & 1;
        const int nxt = cur ^ 1;

        // issue next tile's LDGs early (latency overlapped with compute below)
        float4 na0, na1, nw0, nw1;
        if (k0i < 15) {
            const int k1 = (k0i + 1) * 16;
            na0 = *(const float4*)(aBase + k1);
            na1 = *(const float4*)(aBase + k1 + 4);
            nw0 = *(const float4*)(wBase + k1);
            nw1 = *(const float4*)(wBase + k1 + 4);
        }

#pragma unroll
        for (int kk = 0; kk < 16; kk++) {
            const float4 ra0 = *(const float4*)&As[cur][kk][ty * 8];
            const float4 ra1 = *(const float4*)&As[cur][kk][ty * 8 + 4];
            const ull* bp = (const ull*)&Bs[cur][kk][tx * 8];
            const ull b0 = bp[0], b1 = bp[1], b2 = bp[2], b3 = bp[3];
            const float a[8] = { ra0.x, ra0.y, ra0.z, ra0.w, ra1.x, ra1.y, ra1.z, ra1.w };
#pragma unroll
            for (int i = 0; i < 8; i++) {
                const ull ai = pack2(a[i], a[i]);
                fma2(acc[i][0], ai, b0);
                fma2(acc[i][1], ai, b1);
                fma2(acc[i][2], ai, b2);
                fma2(acc[i][3], ai, b3);
            }
        }

        if (k0i < 15) {
            As[nxt][ldC + 0][ldRow] = na0.x; As[nxt][ldC + 1][ldRow] = na0.y;
            As[nxt][ldC + 2][ldRow] = na0.z; As[nxt][ldC + 3][ldRow] = na0.w;
            As[nxt][ldC + 4][ldRow] = na1.x; As[nxt][ldC + 5][ldRow] = na1.y;
            As[nxt][ldC + 6][ldRow] = na1.z; As[nxt][ldC + 7][ldRow] = na1.w;
            Bs[nxt][ldC + 0][ldRow] = nw0.x; Bs[nxt][ldC + 1][ldRow] = nw0.y;
            Bs[nxt][ldC + 2][ldRow] = nw0.z; Bs[nxt][ldC + 3][ldRow] = nw0.w;
            Bs[nxt][ldC + 4][ldRow] = nw1.x; Bs[nxt][ldC + 5][ldRow] = nw1.y;
            Bs[nxt][ldC + 6][ldRow] = nw1.z; Bs[nxt][ldC + 7][ldRow] = nw1.w;
        }
        __syncthreads();
    }

    // epilogue: biases + store
    const int nc = nb + tx * 8;
    const float4 ba0 = *(const float4*)&b1p[nc];
    const float4 ba1 = *(const float4*)&b1p[nc + 4];
    const float4 bb0 = *(const float4*)&b2p[nc];
    const float4 bb1 = *(const float4*)&b2p[nc + 4];
    const float bias[8] = { ba0.x + bb0.x, ba0.y + bb0.y, ba0.z + bb0.z, ba0.w + bb0.w,
                            ba1.x + bb1.x, ba1.y + bb1.y, ba1.z + bb1.z, ba1.w + bb1.w };
#pragma unroll
    for (int i = 0; i < 8; i++) {
        const size_t m = m0 + ty * 8 + i;
        const float2 p0 = unpack2(acc[i][0]);
        const float2 p1 = unpack2(acc[i][1]);
        const float2 p2 = unpack2(acc[i][2]);
        const float2 p3 = unpack2(acc[i][3]);
        float4 v0, v1;
        v0.x = p0.x + bias[0]; v0.y = p0.y + bias[1];
        v0.z = p1.x + bias[2]; v0.w = p1.y + bias[3];
        v1.x = p2.x + bias[4]; v1.y = p2.y + bias[5];
        v1.z = p3.x + bias[6]; v1.w = p3.y + bias[7];
        *(float4*)&g_xp[m * 1024 + n0 + tx * 8]     = v0;
        *(float4*)&g_xp[m * 1024 + n0 + tx * 8 + 4] = v1;
    }
}

// ---------------------------------------------------------------------------
// Kernel 3: LSTM recurrence. One block per (dir,b) = 128 blocks, 512 threads.
// w_hh row j split: k[0..79] in registers (40 ull pairs), k[80..127] in smem
// (24 pairs, [k2][j] layout -> conflict-free). All matvec via FFMA2.
// (Unchanged from round 5 — awaiting its profile.)
// ---------------------------------------------------------------------------
#define RP 40   // register k-pairs
#define SP 24   // smem k-pairs

__global__ void __launch_bounds__(512) lstm_kernel(
    const float* __restrict__ whf, const float* __restrict__ whb)
{
    extern __shared__ char smraw[];
    ull*   w2    = (ull*)smraw;                 // [SP][512]  = 96 KB
    float* h_sh  = (float*)(w2 + SP * 512);     // [128] (16B aligned)
    float* c_sh  = h_sh + 128;                  // [128]
    float* gates = c_sh + 128;                  // [512]

    const int bid = blockIdx.x;
    const int dir = bid >> 6;
    const int b   = bid & 63;
    const float* __restrict__ wh = dir ? whb : whf;
    const int j = threadIdx.x;

    ull wreg[RP];
    const ull* whu = (const ull*)(wh + (size_t)j * HID);  // row j as 64 k-pairs
#pragma unroll
    for (int k = 0; k < RP; k++) wreg[k] = whu[k];
    for (int k = 0; k < SP; k++) w2[k * 512 + j] = whu[RP + k];

    if (j < HID) { h_sh[j] = 0.0f; c_sh[j] = 0.0f; }
    __syncthreads();

    const int t0 = dir ? (NUTT - 1) : 0;
    float xpv = g_xp[((size_t)t0 * BATCH + b) * 1024 + dir * 512 + j];

    for (int s = 0; s < NUTT; s++) {
        const int t = dir ? (NUTT - 1 - s) : s;
        // prefetch next step's xp (off the critical path)
        float xp_next = 0.0f;
        if (s + 1 < NUTT) {
            const int tn = dir ? (NUTT - 2 - s) : (s + 1);
            xp_next = g_xp[((size_t)tn * BATCH + b) * 1024 + dir * 512 + j];
        }

        ull acc0 = pack2(xpv, 0.0f);
        ull acc1 = pack2(0.0f, 0.0f);
        const ulonglong2* hp = (const ulonglong2*)h_sh;  // 32 x (2 k-pairs)
#pragma unroll
        for (int q = 0; q < RP / 2; q++) {               // k pairs 0..39
            const ulonglong2 hv = hp[q];
            fma2(acc0, wreg[2 * q],     hv.x);
            fma2(acc1, wreg[2 * q + 1], hv.y);
        }
#pragma unroll
        for (int q = 0; q < SP / 2; q++) {               // k pairs 40..63
            const ulonglong2 hv = hp[RP / 2 + q];
            fma2(acc0, w2[(2 * q) * 512 + j],     hv.x);
            fma2(acc1, w2[(2 * q + 1) * 512 + j], hv.y);
        }
        const float2 s0 = unpack2(acc0);
        const float2 s1 = unpack2(acc1);
        gates[j] = (s0.x + s1.x) + (s0.y + s1.y);
        __syncthreads();

        if (j < HID) {
            const float ig = sigf(gates[j]);
            const float fg = sigf(gates[128 + j]);
            const float gg = tanhf(gates[256 + j]);
            const float og = sigf(gates[384 + j]);
            const float c  = fg * c_sh[j] + ig * gg;
            c_sh[j] = c;
            const float h = og * tanhf(c);
            h_sh[j] = h;
            g_h[((size_t)dir * MROWS + (size_t)t * BATCH + b) * HID + j] = h;
        }
        __syncthreads();
        xpv = xp_next;
    }
}

// ---------------------------------------------------------------------------
// Kernel 4: output head + fused mask expansion. One warp per (t,b).
// After the butterfly reduce every lane holds the full logits; lanes 0-15
// write the 16 masked tokens of this utterance directly (mask_kernel fused).
// ---------------------------------------------------------------------------
__global__ void head_kernel(const float* __restrict__ wout,
                            const float* __restrict__ bout,
                            const int* __restrict__ x,
                            float* __restrict__ out)
{
    const int warp = threadIdx.x >> 5;
    const int lane = threadIdx.x & 31;
    const int m = blockIdx.x * 8 + warp;   // m = k*64 + b
    if (m >= MROWS) return;

    const float* hf = g_h + (size_t)m * HID;
    const float* hb = g_h + ((size_t)MROWS + m) * HID;
    const int e = lane * 4;

    const float4 f4 = *(const float4*)&hf[e];
    const float4 b4 = *(const float4*)&hb[e];
    const float4 w0f = *(const float4*)&wout[e];
    const float4 w0b = *(const float4*)&wout[128 + e];
    const float4 w1f = *(const float4*)&wout[256 + e];
    const float4 w1b = *(const float4*)&wout[256 + 128 + e];

    float l0 = f4.x * w0f.x + f4.y * w0f.y + f4.z * w0f.z + f4.w * w0f.w
             + b4.x * w0b.x + b4.y * w0b.y + b4.z * w0b.z + b4.w * w0b.w;
    float l1 = f4.x * w1f.x + f4.y * w1f.y + f4.z * w1f.z + f4.w * w1f.w
             + b4.x * w1b.x + b4.y * w1b.y + b4.z * w1b.z + b4.w * w1b.w;

#pragma unroll
    for (int off = 16; off > 0; off >>= 1) {
        l0 += __shfl_xor_sync(0xFFFFFFFFu, l0, off);
        l1 += __shfl_xor_sync(0xFFFFFFFFu, l1, off);
    }

    l0 += bout[0];
    l1 += bout[1];
    const int idx = (l1 > l0) ? 1 : 0;   // argmax, first-index on tie

    if (lane == 0) {
        const float mm = fmaxf(l0, l1);
        const float e0 = expf(l0 - mm);
        const float e1 = expf(l1 - mm);
        const float inv = 1.0f / (e0 + e1);
        const float p0 = e0 * inv;
        const float p1 = e1 * inv;

        out[m * 2 + 0] = l0;                 // logits
        out[m * 2 + 1] = l1;
        out[16384 + m * 2 + 0] = p0;         // policy
        out[16384 + m * 2 + 1] = p1;
        out[32768 + m] = idx ? p1 : p0;      // chosen_policy
        out[40960 + m] = (float)idx;         // u_mask
    }

    // fused mask expansion: this utterance covers tokens t = k*16 + 0..15
    if (lane < 16) {
        const int k = m >> 6;
        const int b = m & 63;
        const int t = k * 16 + lane;
        const int xi = t * BATCH + b;
        out[49152 + xi] = idx ? (float)x[xi] : 0.0f;
    }
}

// ---------------------------------------------------------------------------
// Launch
// Inputs (metadata order): x, emb, w_ih_f, w_hh_f, b_ih_f, b_hh_f,
//                          w_ih_b, w_hh_b, b_ih_b, b_hh_b, w_out, b_out
// ---------------------------------------------------------------------------
extern "C" void kernel_launch(void* const* d_in, const int* in_sizes, int n_in,
                              void* d_out, int out_size)
{
    const int*   x     = (const int*)  d_in[0];
    const float* emb   = (const float*)d_in[1];
    const float* wih_f = (const float*)d_in[2];
    const float* whh_f = (const float*)d_in[3];
    const float* bih_f = (const float*)d_in[4];
    const float* bhh_f = (const float*)d_in[5];
    const float* wih_b = (const float*)d_in[6];
    const float* whh_b = (const float*)d_in[7];
    const float* bih_b = (const float*)d_in[8];
    const float* bhh_b = (const float*)d_in[9];
    const float* wout  = (const float*)d_in[10];
    const float* bout  = (const float*)d_in[11];
    float* out = (float*)d_out;

    // slot 0
    pool_kernel<<<dim3(BATCH, NUTT), 256>>>(x, emb);

    // slot 1
    gemm_xp_kernel<<<dim3(8, 64), 256>>>(wih_f, wih_b, bih_f, bhh_f, bih_b, bhh_b);

    // slot 2: dummy, rotates lstm into the ncu-captured slot (position 3)
    slot_kernel<<<1, 32>>>();

    // slot 3
    const int lstm_smem = SP * 512 * (int)sizeof(ull) + (128 + 128 + 512) * (int)sizeof(float);
    cudaFuncSetAttribute(lstm_kernel, cudaFuncAttributeMaxDynamicSharedMemorySize, lstm_smem);
    lstm_kernel<<<128, 512, lstm_smem>>>(whh_f, whh_b);

    // slot 4: head + fused mask
    head_kernel<<<1024, 256>>>(wout, bout, x, out);
}